// round 4
// baseline (speedup 1.0000x reference)
#include <cuda_runtime.h>
#include <math.h>

#define Bb   4
#define Hh   8
#define Tt   8192
#define Dd   64
#define Cc   64
#define Ww   128
#define BH   (Bb*Hh)
#define NROW (BH*Cc)
#define NOUT (BH*Tt*Dd)
#define QP 68
#define DP 132

__device__ float  g_dists[(size_t)NROW * Tt];
__device__ int    g_idx[NROW * Ww];
__device__ float  g_cnt[BH * Tt];
__device__ double g_loss;

// ------------------------------------------------------------------
// Phase 1: dists = l2norm(qk) @ means^T, best-cluster loss accumulate
// ------------------------------------------------------------------
__global__ void __launch_bounds__(128) k_dists(const float* __restrict__ qk,
                                               const float* __restrict__ means)
{
    __shared__ float sM[Cc * Dd];
    __shared__ float sMsq[Cc];
    __shared__ float sRed[128];

    const int bh  = blockIdx.y;
    const int h   = bh & (Hh - 1);
    const int tid = threadIdx.x;
    const int tok = blockIdx.x * 128 + tid;

    {
        const float4* src = (const float4*)(means + (size_t)h * Cc * Dd);
        float4* dst = (float4*)sM;
        for (int g = tid; g < Cc * Dd / 4; g += 128) dst[g] = src[g];
    }
    __syncthreads();
    if (tid < Cc) {
        float s = 0.f;
        const float* r = sM + tid * Dd;
        #pragma unroll
        for (int d = 0; d < Dd; d++) s = fmaf(r[d], r[d], s);
        sMsq[tid] = s;
    }
    __syncthreads();

    float4 r[16];
    const float4* qrow = (const float4*)(qk + ((size_t)bh * Tt + tok) * Dd);
    #pragma unroll
    for (int i = 0; i < 16; i++) r[i] = qrow[i];
    float nsq = 0.f;
    #pragma unroll
    for (int i = 0; i < 16; i++)
        nsq += r[i].x * r[i].x + r[i].y * r[i].y + r[i].z * r[i].z + r[i].w * r[i].w;
    const float inv = 1.0f / fmaxf(sqrtf(nsq), 1e-12f);
    #pragma unroll
    for (int i = 0; i < 16; i++) {  // kr = qk * inv (match JAX op order)
        r[i].x *= inv; r[i].y *= inv; r[i].z *= inv; r[i].w *= inv;
    }

    float best = -3.402823e38f;
    int   bc   = 0;
    float* drow = g_dists + (size_t)bh * Cc * Tt + tok;

    #pragma unroll 2
    for (int c = 0; c < Cc; c++) {
        const float4* m4 = (const float4*)(sM + c * Dd);
        float a0 = 0.f, a1 = 0.f, a2 = 0.f, a3 = 0.f;
        #pragma unroll
        for (int i = 0; i < 16; i++) {
            float4 m = m4[i];
            a0 = fmaf(r[i].x, m.x, a0);
            a1 = fmaf(r[i].y, m.y, a1);
            a2 = fmaf(r[i].z, m.z, a2);
            a3 = fmaf(r[i].w, m.w, a3);
        }
        float dist = (a0 + a1) + (a2 + a3);
        drow[(size_t)c * Tt] = dist;
        if (dist > best) { best = dist; bc = c; }
    }

    // ||kr - m_best||^2 = |kr|^2 - 2*dist + |m|^2 ; |kr|^2 = nsq*inv*inv
    sRed[tid] = nsq * inv * inv - 2.0f * best + sMsq[bc];
    __syncthreads();
    for (int s = 64; s > 0; s >>= 1) {
        if (tid < s) sRed[tid] += sRed[tid + s];
        __syncthreads();
    }
    if (tid == 0) atomicAdd(&g_loss, (double)sRed[0]);
}

// ------------------------------------------------------------------
// Phase 2: exact top-128 per row, ascending-index output.
// Radix-select on monotone uint keys; ties -> lowest index.
// ------------------------------------------------------------------
__global__ void __launch_bounds__(256) k_topk()
{
    __shared__ unsigned sk[Tt];
    __shared__ unsigned hist[256];
    __shared__ unsigned sg[256];
    __shared__ unsigned se[256];
    __shared__ unsigned s_pivot;
    __shared__ int      s_need;

    const int row = blockIdx.x;
    const int tid = threadIdx.x;
    const float* src = g_dists + (size_t)row * Tt;

    for (int i = tid; i < Tt; i += 256) {
        unsigned u = __float_as_uint(src[i]);
        u ^= (u & 0x80000000u) ? 0xFFFFFFFFu : 0x80000000u;
        sk[i] = u;
    }

    unsigned prefix = 0;
    int remaining = Ww;
    for (int pass = 0; pass < 4; pass++) {
        const int shift = 24 - pass * 8;
        const unsigned himask = (pass == 0) ? 0u : (0xFFFFFFFFu << (shift + 8));
        hist[tid] = 0;
        __syncthreads();
        for (int i = tid; i < Tt; i += 256) {
            unsigned u = sk[i];
            if ((u & himask) == prefix) atomicAdd(&hist[(u >> shift) & 255], 1u);
        }
        __syncthreads();
        if (tid == 0) {
            int cum = 0;
            int b = 255;
            for (; b > 0; b--) {
                int cc = (int)hist[b];
                if (cum + cc >= remaining) break;
                cum += cc;
            }
            s_pivot = prefix | ((unsigned)b << shift);
            s_need  = remaining - cum;
        }
        __syncthreads();
        prefix    = s_pivot;
        remaining = s_need;
    }
    const unsigned pivot = prefix;
    const int need_eq = remaining;

    int gt = 0, eq = 0;
    const int base = tid * 32;
    for (int j = 0; j < 32; j++) {
        unsigned u = sk[base + j];
        gt += (u > pivot);
        eq += (u == pivot);
    }
    sg[tid] = (unsigned)gt;
    se[tid] = (unsigned)eq;
    __syncthreads();
    if (tid == 0) {
        unsigned ag = 0, ae = 0;
        for (int i = 0; i < 256; i++) {
            unsigned tg = sg[i], te = se[i];
            sg[i] = ag; se[i] = ae;
            ag += tg; ae += te;
        }
    }
    __syncthreads();

    int gb = (int)sg[tid], eb = (int)se[tid];
    int* outp = g_idx + row * Ww;
    for (int j = 0; j < 32; j++) {
        int e = base + j;
        unsigned u = sk[e];
        if (u > pivot) {
            outp[gb + min(eb, need_eq)] = e;
            gb++;
        } else if (u == pivot) {
            if (eb < need_eq) outp[gb + eb] = e;
            eb++;
        }
    }
}

// ------------------------------------------------------------------
// Phase 3: per-cluster attention; 1 block/(b,h,c), 512 thr, warp-local rows
// ------------------------------------------------------------------
__global__ void __launch_bounds__(512, 1) k_attn(const float* __restrict__ qk,
                                                 const float* __restrict__ v,
                                                 const float* __restrict__ relw,
                                                 float* __restrict__ out)
{
    extern __shared__ float sm[];
    float* sQ   = sm;                    // [128][QP]
    float* sV   = sQ + 128 * QP;         // [128][QP]
    float* sB   = sV + 128 * QP;         // [128][QP] rel_w[:,h,:]*scale
    float* sD   = sB + 128 * QP;         // [128][DP]
    float* sInv = sD + 128 * DP;         // 128
    float* sRow = sInv + 128;            // 128
    int*   sIdx = (int*)(sRow + 128);    // 128

    const int blk = blockIdx.x;
    const int bh  = blk >> 6;
    const int h   = bh & (Hh - 1);
    const int tid = threadIdx.x;
    const int l   = tid & 31;
    const int w   = tid >> 5;

    if (tid < 128) sIdx[tid] = g_idx[blk * Ww + tid];
    __syncthreads();

    const float* qkb = qk + (size_t)bh * Tt * Dd;
    const float* vb  = v  + (size_t)bh * Tt * Dd;
    for (int g = tid; g < 128 * 16; g += 512) {
        int r = g >> 4, c4 = (g & 15) << 2;
        int off = sIdx[r] * Dd + c4;
        *(float4*)(sQ + r * QP + c4) = *(const float4*)(qkb + off);
        *(float4*)(sV + r * QP + c4) = *(const float4*)(vb + off);
        float4 rw = *(const float4*)(relw + (r * Hh + h) * Dd + c4);
        rw.x *= 0.125f; rw.y *= 0.125f; rw.z *= 0.125f; rw.w *= 0.125f;
        *(float4*)(sB + r * QP + c4) = rw;
    }
    __syncthreads();
    if (tid < 128) {
        float s = 0.f;
        const float* row = sQ + tid * QP;
        #pragma unroll
        for (int d = 0; d < Dd; d++) s = fmaf(row[d], row[d], s);
        sInv[tid] = 0.125f / fmaxf(sqrtf(s), 1e-12f);
    }
    __syncthreads();

    const int p0 = 8 * w;

    // S[p][q'] = (q_p . q_q') * (scale/||k_q'||)
    {
        float acc[8][4];
        #pragma unroll
        for (int i = 0; i < 8; i++)
            #pragma unroll
            for (int j = 0; j < 4; j++) acc[i][j] = 0.f;
        #pragma unroll 2
        for (int dd = 0; dd < Dd; dd += 4) {
            float4 qf[8], kf[4];
            #pragma unroll
            for (int i = 0; i < 8; i++) qf[i] = *(const float4*)(sQ + (p0 + i) * QP + dd);
            #pragma unroll
            for (int j = 0; j < 4; j++) kf[j] = *(const float4*)(sQ + (l + 32 * j) * QP + dd);
            #pragma unroll
            for (int i = 0; i < 8; i++)
                #pragma unroll
                for (int j = 0; j < 4; j++) {
                    acc[i][j] = fmaf(qf[i].x, kf[j].x, acc[i][j]);
                    acc[i][j] = fmaf(qf[i].y, kf[j].y, acc[i][j]);
                    acc[i][j] = fmaf(qf[i].z, kf[j].z, acc[i][j]);
                    acc[i][j] = fmaf(qf[i].w, kf[j].w, acc[i][j]);
                }
        }
        #pragma unroll
        for (int j = 0; j < 4; j++) {
            float sc = sInv[l + 32 * j];
            #pragma unroll
            for (int i = 0; i < 8; i++) sD[(p0 + i) * DP + (l + 32 * j)] = acc[i][j] * sc;
        }
    }
    __syncwarp();

    // R[p][r] = q_p . relw_r ; fold _shift: dots[p][p+r-127] += R[p][r]
    {
        float acc[8][4];
        #pragma unroll
        for (int i = 0; i < 8; i++)
            #pragma unroll
            for (int j = 0; j < 4; j++) acc[i][j] = 0.f;
        #pragma unroll 2
        for (int dd = 0; dd < Dd; dd += 4) {
            float4 qf[8], bf[4];
            #pragma unroll
            for (int i = 0; i < 8; i++) qf[i] = *(const float4*)(sQ + (p0 + i) * QP + dd);
            #pragma unroll
            for (int j = 0; j < 4; j++) bf[j] = *(const float4*)(sB + (l + 32 * j) * QP + dd);
            #pragma unroll
            for (int i = 0; i < 8; i++)
                #pragma unroll
                for (int j = 0; j < 4; j++) {
                    acc[i][j] = fmaf(qf[i].x, bf[j].x, acc[i][j]);
                    acc[i][j] = fmaf(qf[i].y, bf[j].y, acc[i][j]);
                    acc[i][j] = fmaf(qf[i].z, bf[j].z, acc[i][j]);
                    acc[i][j] = fmaf(qf[i].w, bf[j].w, acc[i][j]);
                }
        }
        #pragma unroll
        for (int i = 0; i < 8; i++) {
            int p = p0 + i;
            #pragma unroll
            for (int j = 0; j < 4; j++) {
                int qc = p + (l + 32 * j) - 127;
                if (qc >= 0) sD[p * DP + qc] += acc[i][j];
            }
        }
    }
    __syncwarp();
    if (l < 8) sD[(p0 + l) * DP + (p0 + l)] = -50000.0f;
    __syncwarp();

    // softmax per row (warp-local)
    #pragma unroll
    for (int i = 0; i < 8; i++) {
        int p = p0 + i;
        float vv[4];
        float mx = -3.402823e38f;
        #pragma unroll
        for (int j = 0; j < 4; j++) {
            vv[j] = sD[p * DP + l + 32 * j];
            mx = fmaxf(mx, vv[j]);
        }
        #pragma unroll
        for (int o = 16; o > 0; o >>= 1) mx = fmaxf(mx, __shfl_xor_sync(0xffffffffu, mx, o));
        float s = 0.f;
        #pragma unroll
        for (int j = 0; j < 4; j++) {
            vv[j] = expf(vv[j] - mx);
            s += vv[j];
            sD[p * DP + l + 32 * j] = vv[j];
        }
        #pragma unroll
        for (int o = 16; o > 0; o >>= 1) s += __shfl_xor_sync(0xffffffffu, s, o);
        if (l == 0) sRow[p] = 1.0f / s;
    }
    __syncwarp();

    // O = attn @ v ; scatter with atomics
    {
        float acc[8][2];
        #pragma unroll
        for (int i = 0; i < 8; i++) { acc[i][0] = 0.f; acc[i][1] = 0.f; }
        #pragma unroll 4
        for (int j = 0; j < 128; j++) {
            float2 vf = *(const float2*)(sV + j * QP + 2 * l);
            #pragma unroll
            for (int i = 0; i < 8; i++) {
                float a = sD[(p0 + i) * DP + j];
                acc[i][0] = fmaf(a, vf.x, acc[i][0]);
                acc[i][1] = fmaf(a, vf.y, acc[i][1]);
            }
        }
        #pragma unroll
        for (int i = 0; i < 8; i++) {
            int p = p0 + i;
            float rinv = sRow[p];
            float* dst = out + ((size_t)bh * Tt + sIdx[p]) * Dd + 2 * l;
            atomicAdd(dst,     acc[i][0] * rinv);
            atomicAdd(dst + 1, acc[i][1] * rinv);
        }
        if (l < 8) atomicAdd(&g_cnt[bh * Tt + sIdx[p0 + l]], 1.0f);
    }
}

// ------------------------------------------------------------------
// Phase 4: out = num / (count + eps); append loss scalar
// ------------------------------------------------------------------
__global__ void __launch_bounds__(256) k_final(float* __restrict__ out, int out_size)
{
    int i = blockIdx.x * blockDim.x + threadIdx.x;
    if (i < NOUT / 4) {
        float c  = g_cnt[i >> 4];
        float rs = 1.0f / (c + 1e-5f);
        float4* p = (float4*)out + i;
        float4 vv = *p;
        vv.x *= rs; vv.y *= rs; vv.z *= rs; vv.w *= rs;
        *p = vv;
    }
    if (i == 0 && out_size > NOUT) {
        out[NOUT] = (float)(g_loss * (1.0e-4 / (double)NOUT));
    }
}

extern "C" void kernel_launch(void* const* d_in, const int* in_sizes, int n_in,
                              void* d_out, int out_size)
{
    const float* qk    = (const float*)d_in[0];
    const float* v     = (const float*)d_in[1];
    const float* means = (const float*)d_in[2];
    const float* relw  = (const float*)d_in[3];
    float* out = (float*)d_out;

    cudaMemsetAsync(d_out, 0, (size_t)out_size * sizeof(float));
    void* cp = 0; cudaGetSymbolAddress(&cp, g_cnt);
    cudaMemsetAsync(cp, 0, (size_t)BH * Tt * sizeof(float));
    void* lp = 0; cudaGetSymbolAddress(&lp, g_loss);
    cudaMemsetAsync(lp, 0, sizeof(double));

    dim3 g1(Tt / 128, BH);
    k_dists<<<g1, 128>>>(qk, means);

    k_topk<<<NROW, 256>>>();

    const int smem_attn = (128 * QP * 3 + 128 * DP + 128 + 128 + 128) * 4;
    cudaFuncSetAttribute(k_attn, cudaFuncAttributeMaxDynamicSharedMemorySize, smem_attn);
    k_attn<<<NROW, 512, smem_attn>>>(qk, v, relw, out);

    k_final<<<NOUT / 4 / 256, 256>>>(out, out_size);
}